// round 1
// baseline (speedup 1.0000x reference)
#include <cuda_runtime.h>
#include <cuda_bf16.h>

// Problem shape (fixed by setup_inputs): x (64, 256, 56, 56) fp32
#define B 64
#define C 256
#define HW 3136            // 56*56
#define HW4 784            // HW/4 float4s per channel
#define BC (B * C)         // 16384

// Scratch: per-(b,c) energy and keep-mask. __device__ globals (no allocation).
__device__ float         g_mag[BC];
__device__ unsigned char g_mask[BC];

// ---------------------------------------------------------------------------
// Kernel 1: magnitude[b,c] = sum over HW of x^2. One block per (b,c).
// ---------------------------------------------------------------------------
__global__ void __launch_bounds__(256) mag_kernel(const float* __restrict__ x) {
    const int bc = blockIdx.x;
    const float4* __restrict__ p =
        reinterpret_cast<const float4*>(x + (size_t)bc * HW);

    float s = 0.0f;
    for (int i = threadIdx.x; i < HW4; i += 256) {
        float4 v = p[i];
        s += v.x * v.x + v.y * v.y + v.z * v.z + v.w * v.w;
    }

    // warp reduce
    #pragma unroll
    for (int o = 16; o > 0; o >>= 1)
        s += __shfl_xor_sync(0xFFFFFFFFu, s, o);

    __shared__ float ws[8];
    if ((threadIdx.x & 31) == 0) ws[threadIdx.x >> 5] = s;
    __syncthreads();

    if (threadIdx.x < 8) {
        float t = ws[threadIdx.x];
        #pragma unroll
        for (int o = 4; o > 0; o >>= 1)
            t += __shfl_xor_sync(0x000000FFu, t, o);
        if (threadIdx.x == 0) g_mag[bc] = t;
    }
}

// ---------------------------------------------------------------------------
// Kernel 2: per batch, bitonic-sort the 256 energies (ascending) in SMEM;
// threshold = sorted_desc[127] = sorted_asc[128]. mask = mag > threshold
// (strict, matching the reference's `magnitude > threshold`).
// One block of 256 threads per batch.
// ---------------------------------------------------------------------------
__global__ void __launch_bounds__(256) thresh_kernel() {
    const int b = blockIdx.x;
    const int t = threadIdx.x;

    __shared__ float s[C];
    const float v = g_mag[b * C + t];
    s[t] = v;
    __syncthreads();

    // Bitonic sort, ascending
    for (int k = 2; k <= C; k <<= 1) {
        for (int j = k >> 1; j > 0; j >>= 1) {
            const int ixj = t ^ j;
            if (ixj > t) {
                const float a  = s[t];
                const float cc = s[ixj];
                const bool  asc = (t & k) == 0;
                if ((a > cc) == asc) { s[t] = cc; s[ixj] = a; }
            }
            __syncthreads();
        }
    }

    // ascending index 128 == descending index 127 (the 128th largest)
    const float thr = s[128];
    g_mask[b * C + t] = (v > thr) ? 1 : 0;
}

// ---------------------------------------------------------------------------
// Kernel 3: masked copy. Kept channels: stream copy. Dropped channels:
// write zeros WITHOUT reading the input (saves ~half the read traffic).
// One block per (b,c).
// ---------------------------------------------------------------------------
__global__ void __launch_bounds__(256) mask_copy_kernel(const float* __restrict__ x,
                                                        float* __restrict__ y) {
    const int bc = blockIdx.x;
    const float4* __restrict__ in  =
        reinterpret_cast<const float4*>(x + (size_t)bc * HW);
    float4* __restrict__ out =
        reinterpret_cast<float4*>(y + (size_t)bc * HW);

    if (g_mask[bc]) {
        for (int i = threadIdx.x; i < HW4; i += 256)
            out[i] = in[i];
    } else {
        const float4 z = make_float4(0.f, 0.f, 0.f, 0.f);
        for (int i = threadIdx.x; i < HW4; i += 256)
            out[i] = z;
    }
}

// ---------------------------------------------------------------------------
extern "C" void kernel_launch(void* const* d_in, const int* in_sizes, int n_in,
                              void* d_out, int out_size) {
    const float* x = (const float*)d_in[0];
    float*       y = (float*)d_out;

    mag_kernel<<<BC, 256>>>(x);
    thresh_kernel<<<B, 256>>>();
    mask_copy_kernel<<<BC, 256>>>(x, y);
}

// round 4
// speedup vs baseline: 1.0495x; 1.0495x over previous
#include <cuda_runtime.h>
#include <cuda_bf16.h>

// Problem shape (fixed by setup_inputs): x (64, 256, 56, 56) fp32
#define B 64
#define C 256
#define HW 3136            // 56*56
#define HW4 784            // HW/4 float4s per channel
#define BC (B * C)         // 16384

#define WARPS_PER_BLOCK 8
#define GRID_WPC (BC / WARPS_PER_BLOCK)   // 2048 blocks, warp-per-channel

// Scratch: per-(b,c) energy and keep-mask. __device__ globals (no allocation).
__device__ float         g_mag[BC];
__device__ unsigned char g_mask[BC];

__device__ __forceinline__ float4 ldcs4(const float4* p) {
    return __ldcs(p);
}
__device__ __forceinline__ void stcs4(float4* p, float4 v) {
    __stcs(p, v);
}

// ---------------------------------------------------------------------------
// Kernel 1: magnitude[b,c] = sum over HW of x^2. One WARP per channel.
// Each lane: 4 independent float4 loads per iteration (MLP=4), 4 accumulators,
// shfl-only reduction. No smem, no syncthreads.
// 784 = 6*128 + 16  ->  6 full batches of (128 float4 per warp), 16-lane tail.
// ---------------------------------------------------------------------------
__global__ void __launch_bounds__(256) mag_kernel(const float* __restrict__ x) {
    const int warp = (blockIdx.x * WARPS_PER_BLOCK) + (threadIdx.x >> 5);
    const int lane = threadIdx.x & 31;
    const float4* __restrict__ p =
        reinterpret_cast<const float4*>(x + (size_t)warp * HW);

    float s0 = 0.f, s1 = 0.f, s2 = 0.f, s3 = 0.f;

    #pragma unroll
    for (int base = 0; base < 768; base += 128) {
        float4 a = ldcs4(p + base + lane);
        float4 b = ldcs4(p + base + lane + 32);
        float4 c = ldcs4(p + base + lane + 64);
        float4 d = ldcs4(p + base + lane + 96);
        s0 += a.x * a.x + a.y * a.y + a.z * a.z + a.w * a.w;
        s1 += b.x * b.x + b.y * b.y + b.z * b.z + b.w * b.w;
        s2 += c.x * c.x + c.y * c.y + c.z * c.z + c.w * c.w;
        s3 += d.x * d.x + d.y * d.y + d.z * d.z + d.w * d.w;
    }
    // tail: indices 768..783 (16 float4s)
    if (lane < 16) {
        float4 a = ldcs4(p + 768 + lane);
        s0 += a.x * a.x + a.y * a.y + a.z * a.z + a.w * a.w;
    }

    float s = (s0 + s1) + (s2 + s3);
    #pragma unroll
    for (int o = 16; o > 0; o >>= 1)
        s += __shfl_xor_sync(0xFFFFFFFFu, s, o);

    if (lane == 0) g_mag[warp] = s;
}

// ---------------------------------------------------------------------------
// Kernel 2: per batch, bitonic-sort the 256 energies (ascending) in SMEM;
// threshold = sorted_desc[127] = sorted_asc[128]. mask = mag > threshold
// (strict, matching the reference's `magnitude > threshold`).
// One block of 256 threads per batch.
// ---------------------------------------------------------------------------
__global__ void __launch_bounds__(256) thresh_kernel() {
    const int b = blockIdx.x;
    const int t = threadIdx.x;

    __shared__ float s[C];
    const float v = g_mag[b * C + t];
    s[t] = v;
    __syncthreads();

    for (int k = 2; k <= C; k <<= 1) {
        for (int j = k >> 1; j > 0; j >>= 1) {
            const int ixj = t ^ j;
            if (ixj > t) {
                const float a  = s[t];
                const float cc = s[ixj];
                const bool  asc = (t & k) == 0;
                if ((a > cc) == asc) { s[t] = cc; s[ixj] = a; }
            }
            __syncthreads();
        }
    }

    const float thr = s[128];   // ascending idx 128 == 128th largest
    g_mask[b * C + t] = (v > thr) ? 1 : 0;
}

// ---------------------------------------------------------------------------
// Kernel 3: masked copy, warp-per-channel. Kept channels: 4xfloat4 batched
// streaming copy. Dropped channels: write zeros WITHOUT reading the input.
// ---------------------------------------------------------------------------
__global__ void __launch_bounds__(256) mask_copy_kernel(const float* __restrict__ x,
                                                        float* __restrict__ y) {
    const int warp = (blockIdx.x * WARPS_PER_BLOCK) + (threadIdx.x >> 5);
    const int lane = threadIdx.x & 31;
    const float4* __restrict__ in  =
        reinterpret_cast<const float4*>(x + (size_t)warp * HW);
    float4* __restrict__ out =
        reinterpret_cast<float4*>(y + (size_t)warp * HW);

    if (g_mask[warp]) {
        #pragma unroll
        for (int base = 0; base < 768; base += 128) {
            float4 a = ldcs4(in + base + lane);
            float4 b = ldcs4(in + base + lane + 32);
            float4 c = ldcs4(in + base + lane + 64);
            float4 d = ldcs4(in + base + lane + 96);
            stcs4(out + base + lane,      a);
            stcs4(out + base + lane + 32, b);
            stcs4(out + base + lane + 64, c);
            stcs4(out + base + lane + 96, d);
        }
        if (lane < 16)
            stcs4(out + 768 + lane, ldcs4(in + 768 + lane));
    } else {
        const float4 z = make_float4(0.f, 0.f, 0.f, 0.f);
        #pragma unroll
        for (int base = 0; base < 768; base += 128) {
            stcs4(out + base + lane,      z);
            stcs4(out + base + lane + 32, z);
            stcs4(out + base + lane + 64, z);
            stcs4(out + base + lane + 96, z);
        }
        if (lane < 16)
            stcs4(out + 768 + lane, z);
    }
}

// ---------------------------------------------------------------------------
extern "C" void kernel_launch(void* const* d_in, const int* in_sizes, int n_in,
                              void* d_out, int out_size) {
    const float* x = (const float*)d_in[0];
    float*       y = (float*)d_out;

    mag_kernel<<<GRID_WPC, 256>>>(x);
    thresh_kernel<<<B, 256>>>();
    mask_copy_kernel<<<GRID_WPC, 256>>>(x, y);
}

// round 5
// speedup vs baseline: 1.0668x; 1.0165x over previous
#include <cuda_runtime.h>
#include <cuda_bf16.h>

// Problem shape (fixed by setup_inputs): x (64, 256, 56, 56) fp32
#define B 64
#define C 256
#define HW 3136            // 56*56
#define HW4 784            // HW/4 float4s per channel
#define BC (B * C)         // 16384

#define WARPS_PER_BLOCK 8
#define GRID_WPC (BC / WARPS_PER_BLOCK)   // 2048 blocks, warp-per-channel

// Scratch: per-(b,c) energy and keep-mask. __device__ globals (no allocation).
__device__ float         g_mag[BC];
__device__ unsigned char g_mask[BC];

__device__ __forceinline__ float4 ldcs4(const float4* p) {
    return __ldcs(p);
}
__device__ __forceinline__ void stcs4(float4* p, float4 v) {
    __stcs(p, v);
}

// ---------------------------------------------------------------------------
// Kernel 1: magnitude[b,c] = sum over HW of x^2. One WARP per channel.
// MLP=8: each lane issues 8 independent float4 loads per iteration,
// 3 iterations (3*8*32 = 768 float4s) + 16-lane tail. 8 accumulators,
// shfl-only reduction. No smem, no syncthreads.
// ---------------------------------------------------------------------------
__global__ void __launch_bounds__(256) mag_kernel(const float* __restrict__ x) {
    const int warp = (blockIdx.x * WARPS_PER_BLOCK) + (threadIdx.x >> 5);
    const int lane = threadIdx.x & 31;
    const float4* __restrict__ p =
        reinterpret_cast<const float4*>(x + (size_t)warp * HW);

    float acc[8];
    #pragma unroll
    for (int k = 0; k < 8; k++) acc[k] = 0.f;

    #pragma unroll
    for (int base = 0; base < 768; base += 256) {
        float4 v[8];
        #pragma unroll
        for (int k = 0; k < 8; k++)
            v[k] = ldcs4(p + base + lane + 32 * k);
        #pragma unroll
        for (int k = 0; k < 8; k++)
            acc[k] += v[k].x * v[k].x + v[k].y * v[k].y
                    + v[k].z * v[k].z + v[k].w * v[k].w;
    }
    // tail: indices 768..783 (16 float4s)
    if (lane < 16) {
        float4 a = ldcs4(p + 768 + lane);
        acc[0] += a.x * a.x + a.y * a.y + a.z * a.z + a.w * a.w;
    }

    float s = ((acc[0] + acc[1]) + (acc[2] + acc[3]))
            + ((acc[4] + acc[5]) + (acc[6] + acc[7]));
    #pragma unroll
    for (int o = 16; o > 0; o >>= 1)
        s += __shfl_xor_sync(0xFFFFFFFFu, s, o);

    if (lane == 0) g_mag[warp] = s;
}

// ---------------------------------------------------------------------------
// Kernel 2: per batch, bitonic-sort the 256 energies (ascending) in SMEM;
// threshold = sorted_desc[127] = sorted_asc[128]. mask = mag > threshold
// (strict, matching the reference's `magnitude > threshold`).
// One block of 256 threads per batch.
// ---------------------------------------------------------------------------
__global__ void __launch_bounds__(256) thresh_kernel() {
    const int b = blockIdx.x;
    const int t = threadIdx.x;

    __shared__ float s[C];
    const float v = g_mag[b * C + t];
    s[t] = v;
    __syncthreads();

    for (int k = 2; k <= C; k <<= 1) {
        for (int j = k >> 1; j > 0; j >>= 1) {
            const int ixj = t ^ j;
            if (ixj > t) {
                const float a  = s[t];
                const float cc = s[ixj];
                const bool  asc = (t & k) == 0;
                if ((a > cc) == asc) { s[t] = cc; s[ixj] = a; }
            }
            __syncthreads();
        }
    }

    const float thr = s[128];   // ascending idx 128 == 128th largest
    g_mask[b * C + t] = (v > thr) ? 1 : 0;
}

// ---------------------------------------------------------------------------
// Kernel 3: masked copy, warp-per-channel, MLP=8. Kept channels: batched
// streaming copy (8 loads then 8 stores per iteration). Dropped channels:
// write zeros WITHOUT reading the input.
// ---------------------------------------------------------------------------
__global__ void __launch_bounds__(256) mask_copy_kernel(const float* __restrict__ x,
                                                        float* __restrict__ y) {
    const int warp = (blockIdx.x * WARPS_PER_BLOCK) + (threadIdx.x >> 5);
    const int lane = threadIdx.x & 31;
    const float4* __restrict__ in  =
        reinterpret_cast<const float4*>(x + (size_t)warp * HW);
    float4* __restrict__ out =
        reinterpret_cast<float4*>(y + (size_t)warp * HW);

    if (g_mask[warp]) {
        #pragma unroll
        for (int base = 0; base < 768; base += 256) {
            float4 v[8];
            #pragma unroll
            for (int k = 0; k < 8; k++)
                v[k] = ldcs4(in + base + lane + 32 * k);
            #pragma unroll
            for (int k = 0; k < 8; k++)
                stcs4(out + base + lane + 32 * k, v[k]);
        }
        if (lane < 16)
            stcs4(out + 768 + lane, ldcs4(in + 768 + lane));
    } else {
        const float4 z = make_float4(0.f, 0.f, 0.f, 0.f);
        #pragma unroll
        for (int base = 0; base < 768; base += 256) {
            #pragma unroll
            for (int k = 0; k < 8; k++)
                stcs4(out + base + lane + 32 * k, z);
        }
        if (lane < 16)
            stcs4(out + 768 + lane, z);
    }
}

// ---------------------------------------------------------------------------
extern "C" void kernel_launch(void* const* d_in, const int* in_sizes, int n_in,
                              void* d_out, int out_size) {
    const float* x = (const float*)d_in[0];
    float*       y = (float*)d_out;

    mag_kernel<<<GRID_WPC, 256>>>(x);
    thresh_kernel<<<B, 256>>>();
    mask_copy_kernel<<<GRID_WPC, 256>>>(x, y);
}